// round 16
// baseline (speedup 1.0000x reference)
#include <cuda_runtime.h>
#include <cuda_fp16.h>
#include <cstdint>

namespace {
constexpr int kB = 128, kS = 2048, kD = 128, kNQ = 18;
constexpr int TS = 128, THREADS = 256;
constexpr int HALF_S = kS / 2, NTILE = HALF_S / TS;   // 1024, 8
constexpr float SCALE = 0.08838834764831845f;   // 1/sqrt(128)
constexpr int PITCH = 272;                      // fp16 row pitch
constexpr int XBUF  = TS * PITCH;               // 34816 B

constexpr int OFF_XH = 0;                       // x fp16 [2][128][272]
constexpr int OFF_Q  = OFF_XH + 2 * XBUF;       // 69632: q fp16 [32][272]
constexpr int OFF_LR = OFF_Q + 32 * PITCH;      // 78336: per-warp row sums
constexpr int OFF_LI = OFF_LR + 512;            // 78848
constexpr int OFF_MB = OFF_LI + 128;            // 78976: mask bytes (1KB)
constexpr int SMEM_BYTES = OFF_MB + 1024;       // 80000 -> 2 CTAs/SM
constexpr int OUT_PER_B = kNQ * kD;
}

__device__ float    g_partP[kB][2][OUT_PER_B];
__device__ float    g_partL[kB][2][kNQ];
__device__ unsigned g_cnt[kB];

__device__ __forceinline__ void ldsm_x4(uint32_t* r, uint32_t a) {
    asm volatile("ldmatrix.sync.aligned.m8n8.x4.shared.b16 {%0,%1,%2,%3},[%4];"
        : "=r"(r[0]), "=r"(r[1]), "=r"(r[2]), "=r"(r[3]) : "r"(a));
}
__device__ __forceinline__ void ldsm_x2(uint32_t* r, uint32_t a) {
    asm volatile("ldmatrix.sync.aligned.m8n8.x2.shared.b16 {%0,%1},[%2];"
        : "=r"(r[0]), "=r"(r[1]) : "r"(a));
}
__device__ __forceinline__ void ldsm_x2t(uint32_t* r, uint32_t a) {
    asm volatile("ldmatrix.sync.aligned.m8n8.x2.trans.shared.b16 {%0,%1},[%2];"
        : "=r"(r[0]), "=r"(r[1]) : "r"(a));
}
__device__ __forceinline__ void mma16816(float* c, const uint32_t* a, const uint32_t* b) {
    asm volatile("mma.sync.aligned.m16n8k16.row.col.f32.f16.f16.f32 "
        "{%0,%1,%2,%3},{%4,%5,%6,%7},{%8,%9},{%0,%1,%2,%3};"
        : "+f"(c[0]), "+f"(c[1]), "+f"(c[2]), "+f"(c[3])
        : "r"(a[0]), "r"(a[1]), "r"(a[2]), "r"(a[3]), "r"(b[0]), "r"(b[1]));
}
__device__ __forceinline__ uint32_t h2u(__half2 h) {
    uint32_t u; *reinterpret_cast<__half2*>(&u) = h; return u;
}

__global__ void __launch_bounds__(THREADS, 2)
AttentionPooling_main(const float* __restrict__ x,
                      const float* __restrict__ qe,
                      const int*   __restrict__ ques,
                      const int*   __restrict__ mask,
                      float*       __restrict__ out)
{
    extern __shared__ char smem[];
    float*   lr = reinterpret_cast<float*>(smem + OFF_LR);
    float*   li = reinterpret_cast<float*>(smem + OFF_LI);
    uint8_t* m8 = reinterpret_cast<uint8_t*>(smem + OFF_MB);
    __shared__ int s_flag;

    const int t = threadIdx.x, w = t >> 5, lane = t & 31;
    const int b = blockIdx.x >> 1, half = blockIdx.x & 1;
    const int qh = w >> 2;                      // q-half (rows qh*16..+15)
    const int sg = w & 3;                       // s-group of 32 in tile
    const int g = lane >> 2, scol = (lane & 3) * 2;
    const uint32_t sb = (uint32_t)__cvta_generic_to_shared(smem);

    const float4* xb4 = reinterpret_cast<const float4*>(
        x + (size_t)b * kS * kD + (size_t)half * HALF_S * kD);

    // ---- batched x staging: 4 batches of 32 rows per tile ----
    float4 xpre[4];
    auto ldg_b = [&](int gb) {                  // global batch = tile*4 + ib
        const float4* src = xb4 + gb * 1024;
        #pragma unroll
        for (int j = 0; j < 4; ++j) xpre[j] = src[t + j * 256];
    };
    auto conv_b = [&](int gb) {
        const int xbase = OFF_XH + ((gb >> 2) & 1) * XBUF;
        const int rb = (gb & 3) * 32;
        #pragma unroll
        for (int j = 0; j < 4; ++j) {
            float4 a = xpre[j];
            int s = rb + w + j * 8;
            uint2 ph = make_uint2(h2u(__floats2half2_rn(a.x, a.y)),
                                  h2u(__floats2half2_rn(a.z, a.w)));
            *reinterpret_cast<uint2*>(smem + xbase + s * PITCH + lane * 8) = ph;
        }
    };

    ldg_b(0);

    // ---- mask half -> bytes ----
    {
        int4 mv = reinterpret_cast<const int4*>(mask + b * kS + half * HALF_S)[t];
        uint32_t pk = (mv.x & 1) | ((mv.y & 1) << 8) |
                      ((mv.z & 1) << 16) | ((mv.w & 1) << 24);
        *reinterpret_cast<uint32_t*>(m8 + t * 4) = pk;
    }
    // ---- q gather: fp16 [32][272], rows >= kNQ zeroed ----
    for (int i = t; i < 32 * 16; i += THREADS) {
        int j = i >> 4, c = i & 15;
        uint4 pk = make_uint4(0u, 0u, 0u, 0u);
        if (j < kNQ) {
            int qi = ques[b * kNQ + j];
            const float4* qr = reinterpret_cast<const float4*>(qe + qi * kD);
            float4 v0 = qr[c * 2], v1 = qr[c * 2 + 1];
            pk.x = h2u(__floats2half2_rn(v0.x * SCALE, v0.y * SCALE));
            pk.y = h2u(__floats2half2_rn(v0.z * SCALE, v0.w * SCALE));
            pk.z = h2u(__floats2half2_rn(v1.x * SCALE, v1.y * SCALE));
            pk.w = h2u(__floats2half2_rn(v1.z * SCALE, v1.w * SCALE));
        }
        *reinterpret_cast<uint4*>(smem + OFF_Q + j * PITCH + c * 16) = pk;
    }

    // ---- prologue: convert tile 0, start batch 4 ----
    conv_b(0); ldg_b(1);
    conv_b(1); ldg_b(2);
    conv_b(2); ldg_b(3);
    conv_b(3); ldg_b(4);
    __syncthreads();

    float co[16][4];
    #pragma unroll
    for (int j = 0; j < 16; ++j)
        co[j][0] = co[j][1] = co[j][2] = co[j][3] = 0.f;
    float lsum0 = 0.f, lsum1 = 0.f;

    for (int tile = 0; tile < NTILE; ++tile) {
        const int xcur = OFF_XH + (tile & 1) * XBUF;
        const bool more = (tile + 1 < NTILE);
        const int nb = 4 * (tile + 1);

        // ---- phase A: scores[16q x 32s own group], qa reloaded per k ----
        float c[4][4];
        #pragma unroll
        for (int j = 0; j < 4; ++j)
            c[j][0] = c[j][1] = c[j][2] = c[j][3] = 0.f;
        #pragma unroll
        for (int k = 0; k < 8; ++k) {
            uint32_t qa[4], bf[4][2];
            ldsm_x4(qa, sb + OFF_Q + (qh * 16 + (lane & 15)) * PITCH
                        + (k * 2 + (lane >> 4)) * 16);
            #pragma unroll
            for (int n = 0; n < 4; ++n)
                ldsm_x2(bf[n], sb + xcur + (sg * 32 + n * 8 + (lane & 7)) * PITCH
                               + (k * 2 + ((lane >> 3) & 1)) * 16);
            #pragma unroll
            for (int n = 0; n < 4; ++n)
                mma16816(c[n], qa, bf[n]);
        }
        if (more) { conv_b(nb); ldg_b(nb + 1); }

        // ---- epilogue in registers: mask+exp -> p A-fragments ----
        uint32_t pa[2][4];
        #pragma unroll
        for (int n = 0; n < 4; ++n) {
            uchar2 mv = *reinterpret_cast<const uchar2*>(
                m8 + tile * TS + sg * 32 + n * 8 + scol);
            float e0 = mv.x ? __expf(c[n][0]) : 0.f;
            float e1 = mv.y ? __expf(c[n][1]) : 0.f;
            float e2 = mv.x ? __expf(c[n][2]) : 0.f;
            float e3 = mv.y ? __expf(c[n][3]) : 0.f;
            lsum0 += e0 + e1; lsum1 += e2 + e3;
            pa[n >> 1][(n & 1) * 2 + 0] = h2u(__floats2half2_rn(e0, e1));
            pa[n >> 1][(n & 1) * 2 + 1] = h2u(__floats2half2_rn(e2, e3));
        }
        if (more) { conv_b(nb + 1); ldg_b(nb + 2); }

        // ---- phase B: co[16q x 128d] += p(own 32s) . x ----
        #pragma unroll
        for (int j2 = 0; j2 < 16; ++j2) {
            uint32_t bh[2];
            ldsm_x2t(bh, sb + xcur + (sg * 32 + (lane & 7)
                         + ((lane >> 3) & 1) * 8) * PITCH + (j2 * 8) * 2);
            mma16816(co[j2], pa[0], bh);
        }
        if (more) { conv_b(nb + 2); ldg_b(nb + 3); }
        #pragma unroll
        for (int j2 = 0; j2 < 16; ++j2) {
            uint32_t bh[2];
            ldsm_x2t(bh, sb + xcur + (sg * 32 + 16 + (lane & 7)
                         + ((lane >> 3) & 1) * 8) * PITCH + (j2 * 8) * 2);
            mma16816(co[j2], pa[1], bh);
        }
        if (more) {
            conv_b(nb + 3);
            if (tile + 2 < NTILE) ldg_b(nb + 4);
        }
        __syncthreads();
    }

    // ---- row sums: quad-reduce, stash per warp ----
    #pragma unroll
    for (int o = 1; o < 4; o <<= 1) {
        lsum0 += __shfl_xor_sync(0xffffffffu, lsum0, o);
        lsum1 += __shfl_xor_sync(0xffffffffu, lsum1, o);
    }
    if ((lane & 3) == 0) {
        lr[w * 16 + g]     = lsum0;
        lr[w * 16 + 8 + g] = lsum1;
    }

    // ---- stash co partials (reuse XH area): red[w][16q][128d] ----
    float* red = reinterpret_cast<float*>(smem);
    __syncthreads();
    #pragma unroll
    for (int j2 = 0; j2 < 16; ++j2) {
        int d = j2 * 8 + scol;
        *reinterpret_cast<float2*>(red + (w * 16 + g) * 128 + d) =
            make_float2(co[j2][0], co[j2][1]);
        *reinterpret_cast<float2*>(red + (w * 16 + 8 + g) * 128 + d) =
            make_float2(co[j2][2], co[j2][3]);
    }
    __syncthreads();

    if (t < 32) {
        int hq = t >> 4, ql = t & 15;
        int q = hq * 16 + ql;
        float s = 0.f;
        #pragma unroll
        for (int r = 0; r < 4; ++r) s += lr[(hq * 4 + r) * 16 + ql];
        if (q < kNQ) g_partL[b][half][q] = s;
    }

    // ---- per-CTA partial output: sum 4 s-group partials ----
    float* P = g_partP[b][half];
    for (int o = t; o < 2 * 16 * 128; o += THREADS) {
        int hq = o >> 11, ql = (o >> 7) & 15, d = o & 127;
        int q = hq * 16 + ql;
        if (q < kNQ) {
            float s = 0.f;
            #pragma unroll
            for (int r = 0; r < 4; ++r)
                s += red[((hq * 4 + r) * 16 + ql) * 128 + d];
            P[q * kD + d] = s;
        }
    }
    __syncthreads();

    // ---- last-arriver combines (proven scheme; counter self-resets) ----
    if (t == 0) {
        __threadfence();
        s_flag = (int)atomicAdd(&g_cnt[b], 1u);
    }
    __syncthreads();
    if (s_flag == 1) {
        __threadfence();
        if (t < kNQ)
            li[t] = 1.0f / (g_partL[b][0][t] + g_partL[b][1][t]);
        __syncthreads();
        const float* P0 = g_partP[b][0];
        const float* P1 = g_partP[b][1];
        float* ob = out + (size_t)b * OUT_PER_B;
        for (int o = t; o < OUT_PER_B; o += THREADS)
            ob[o] = (P0[o] + P1[o]) * li[o >> 7];
        if (t == 0) g_cnt[b] = 0;
    }
}

extern "C" void kernel_launch(void* const* d_in, const int* in_sizes, int n_in,
                              void* d_out, int out_size) {
    const float* x    = (const float*)d_in[0];
    const float* qe   = (const float*)d_in[1];
    const int*   ques = (const int*)d_in[2];
    const int*   mask = (const int*)d_in[3];
    float* out = (float*)d_out;

    cudaFuncSetAttribute(AttentionPooling_main,
                         cudaFuncAttributeMaxDynamicSharedMemorySize, SMEM_BYTES);
    AttentionPooling_main<<<2 * kB, THREADS, SMEM_BYTES>>>(x, qe, ques, mask, out);
}

// round 17
// speedup vs baseline: 1.1156x; 1.1156x over previous
#include <cuda_runtime.h>
#include <cuda_fp16.h>
#include <cstdint>

namespace {
constexpr int kB = 128, kS = 2048, kD = 128, kNQ = 18;
constexpr int TS = 128, NTILE = kS / TS, THREADS = 512;
constexpr float SCALE = 0.08838834764831845f;   // 1/sqrt(128)
constexpr int PITCH = 272;                      // fp16 row pitch
constexpr int XBUF  = TS * PITCH;               // 34816 B

constexpr int OFF_XH = 0;                       // x fp16 [2][128][272]
constexpr int OFF_Q  = OFF_XH + 2 * XBUF;       // 69632: q fp16 [32][272]
// red scratch reuses [0, 131072) after the loop; control data lives above it
constexpr int OFF_LR = 131072;                  // 16 warps x 16 rows (1KB)
constexpr int OFF_LI = OFF_LR + 1024;
constexpr int OFF_MB = OFF_LI + 128;            // mask bytes (2KB)
constexpr int SMEM_BYTES = OFF_MB + 2048;       // 134272
constexpr int OUT_PER_B = kNQ * kD;
}

__device__ __forceinline__ void ldsm_x4(uint32_t* r, uint32_t a) {
    asm volatile("ldmatrix.sync.aligned.m8n8.x4.shared.b16 {%0,%1,%2,%3},[%4];"
        : "=r"(r[0]), "=r"(r[1]), "=r"(r[2]), "=r"(r[3]) : "r"(a));
}
__device__ __forceinline__ void ldsm_x2(uint32_t* r, uint32_t a) {
    asm volatile("ldmatrix.sync.aligned.m8n8.x2.shared.b16 {%0,%1},[%2];"
        : "=r"(r[0]), "=r"(r[1]) : "r"(a));
}
__device__ __forceinline__ void ldsm_x2t(uint32_t* r, uint32_t a) {
    asm volatile("ldmatrix.sync.aligned.m8n8.x2.trans.shared.b16 {%0,%1},[%2];"
        : "=r"(r[0]), "=r"(r[1]) : "r"(a));
}
__device__ __forceinline__ void mma16816(float* c, const uint32_t* a, const uint32_t* b) {
    asm volatile("mma.sync.aligned.m16n8k16.row.col.f32.f16.f16.f32 "
        "{%0,%1,%2,%3},{%4,%5,%6,%7},{%8,%9},{%0,%1,%2,%3};"
        : "+f"(c[0]), "+f"(c[1]), "+f"(c[2]), "+f"(c[3])
        : "r"(a[0]), "r"(a[1]), "r"(a[2]), "r"(a[3]), "r"(b[0]), "r"(b[1]));
}
__device__ __forceinline__ uint32_t h2u(__half2 h) {
    uint32_t u; *reinterpret_cast<__half2*>(&u) = h; return u;
}

__global__ void __launch_bounds__(THREADS, 1)
AttentionPooling_main(const float* __restrict__ x,
                      const float* __restrict__ qe,
                      const int*   __restrict__ ques,
                      const int*   __restrict__ mask,
                      float*       __restrict__ out)
{
    extern __shared__ char smem[];
    float*   lr = reinterpret_cast<float*>(smem + OFF_LR);
    float*   li = reinterpret_cast<float*>(smem + OFF_LI);
    uint8_t* m8 = reinterpret_cast<uint8_t*>(smem + OFF_MB);

    const int t = threadIdx.x, w = t >> 5, lane = t & 31;
    const int b = blockIdx.x;
    const int qh = w >> 3;                      // q-half (rows qh*16..+15)
    const int sg = w & 7;                       // s-group of 16 within tile
    const int g = lane >> 2, scol = (lane & 3) * 2;
    const uint32_t sb = (uint32_t)__cvta_generic_to_shared(smem);

    const float4* xb4 = reinterpret_cast<const float4*>(x + (size_t)b * kS * kD);

    // ---- half-tile register staging: 4 float4/thread at 512 threads ----
    float4 xpre[4];
    auto ldg_h = [&](int tile, int h) {
        const float4* src = xb4 + tile * 4096 + h * 2048;
        #pragma unroll
        for (int j = 0; j < 4; ++j) xpre[j] = src[t + j * THREADS];
    };
    auto conv_h = [&](int xbase, int h) {       // rows h*64 .. h*64+63
        #pragma unroll
        for (int j = 0; j < 4; ++j) {
            float4 a = xpre[j];
            int s = h * 64 + w + j * 16;
            uint2 ph = make_uint2(h2u(__floats2half2_rn(a.x, a.y)),
                                  h2u(__floats2half2_rn(a.z, a.w)));
            *reinterpret_cast<uint2*>(smem + xbase + s * PITCH + lane * 8) = ph;
        }
    };

    ldg_h(0, 0);

    // ---- mask -> bytes (512 int4 = one per thread) ----
    {
        int4 mv = reinterpret_cast<const int4*>(mask + b * kS)[t];
        uint32_t pk = (mv.x & 1) | ((mv.y & 1) << 8) |
                      ((mv.z & 1) << 16) | ((mv.w & 1) << 24);
        *reinterpret_cast<uint32_t*>(m8 + t * 4) = pk;
    }
    // ---- q gather: fp16 [32][272], rows >= kNQ zeroed (512 = one each) ----
    {
        int j = t >> 4, c = t & 15;
        uint4 pk = make_uint4(0u, 0u, 0u, 0u);
        if (j < kNQ) {
            int qi = ques[b * kNQ + j];
            const float4* qr = reinterpret_cast<const float4*>(qe + qi * kD);
            float4 v0 = qr[c * 2], v1 = qr[c * 2 + 1];
            pk.x = h2u(__floats2half2_rn(v0.x * SCALE, v0.y * SCALE));
            pk.y = h2u(__floats2half2_rn(v0.z * SCALE, v0.w * SCALE));
            pk.z = h2u(__floats2half2_rn(v1.x * SCALE, v1.y * SCALE));
            pk.w = h2u(__floats2half2_rn(v1.z * SCALE, v1.w * SCALE));
        }
        *reinterpret_cast<uint4*>(smem + OFF_Q + j * PITCH + c * 16) = pk;
    }

    // ---- prologue: stage tile 0 fully, start h0 of tile 1 ----
    conv_h(OFF_XH, 0);
    ldg_h(0, 1);
    conv_h(OFF_XH, 1);
    ldg_h(1, 0);
    __syncthreads();

    float co[16][4];
    #pragma unroll
    for (int j = 0; j < 16; ++j)
        co[j][0] = co[j][1] = co[j][2] = co[j][3] = 0.f;
    float lsum0 = 0.f, lsum1 = 0.f;

    for (int tile = 0; tile < NTILE; ++tile) {
        const int xcur = OFF_XH + (tile & 1) * XBUF;
        const int xnxt = OFF_XH + ((tile + 1) & 1) * XBUF;
        const bool more = (tile + 1 < NTILE);

        // ---- phase A: scores[16q x 16s own group] ----
        float c[2][4];
        c[0][0] = c[0][1] = c[0][2] = c[0][3] = 0.f;
        c[1][0] = c[1][1] = c[1][2] = c[1][3] = 0.f;
        #pragma unroll
        for (int k = 0; k < 8; ++k) {
            uint32_t qa[4], bf[2][2];
            ldsm_x4(qa, sb + OFF_Q + (qh * 16 + (lane & 15)) * PITCH
                        + (k * 2 + (lane >> 4)) * 16);
            #pragma unroll
            for (int n = 0; n < 2; ++n)
                ldsm_x2(bf[n], sb + xcur + (sg * 16 + n * 8 + (lane & 7)) * PITCH
                               + (k * 2 + ((lane >> 3) & 1)) * 16);
            mma16816(c[0], qa, bf[0]);
            mma16816(c[1], qa, bf[1]);
        }

        // convert h0 of next tile (loaded a full tile ago); start ldg h1
        if (more) { conv_h(xnxt, 0); ldg_h(tile + 1, 1); }

        // ---- epilogue in registers: mask+exp -> p A-fragment (one k16) ----
        uint32_t pa[4];
        #pragma unroll
        for (int n = 0; n < 2; ++n) {
            uchar2 mv = *reinterpret_cast<const uchar2*>(
                m8 + tile * TS + sg * 16 + n * 8 + scol);
            float e0 = mv.x ? __expf(c[n][0]) : 0.f;
            float e1 = mv.y ? __expf(c[n][1]) : 0.f;
            float e2 = mv.x ? __expf(c[n][2]) : 0.f;
            float e3 = mv.y ? __expf(c[n][3]) : 0.f;
            lsum0 += e0 + e1; lsum1 += e2 + e3;
            pa[n * 2 + 0] = h2u(__floats2half2_rn(e0, e1));
            pa[n * 2 + 1] = h2u(__floats2half2_rn(e2, e3));
        }

        // ---- phase B: co[16q x 128d] += p(own 16s) . x ----
        #pragma unroll
        for (int j2 = 0; j2 < 16; ++j2) {
            uint32_t bh[2];
            ldsm_x2t(bh, sb + xcur + (sg * 16 + (lane & 7)
                         + ((lane >> 3) & 1) * 8) * PITCH + (j2 * 8) * 2);
            mma16816(co[j2], pa, bh);
        }

        // convert h1 of next tile; start ldg h0 of tile+2
        if (more) {
            conv_h(xnxt, 1);
            if (tile + 2 < NTILE) ldg_h(tile + 2, 0);
        }
        __syncthreads();    // one barrier per tile
    }

    // ---- row sums: quad-reduce, stash per warp ----
    #pragma unroll
    for (int o = 1; o < 4; o <<= 1) {
        lsum0 += __shfl_xor_sync(0xffffffffu, lsum0, o);
        lsum1 += __shfl_xor_sync(0xffffffffu, lsum1, o);
    }
    if ((lane & 3) == 0) {
        lr[w * 16 + g]     = lsum0;
        lr[w * 16 + 8 + g] = lsum1;
    }

    // ---- stash co partials: red[w][16q][128d] (128KB, reuses XH+Q) ----
    float* red = reinterpret_cast<float*>(smem);
    __syncthreads();
    #pragma unroll
    for (int j2 = 0; j2 < 16; ++j2) {
        int d = j2 * 8 + scol;
        *reinterpret_cast<float2*>(red + (w * 16 + g) * 128 + d) =
            make_float2(co[j2][0], co[j2][1]);
        *reinterpret_cast<float2*>(red + (w * 16 + 8 + g) * 128 + d) =
            make_float2(co[j2][2], co[j2][3]);
    }
    __syncthreads();

    if (t < 32) {
        int hq = t >> 4, ql = t & 15;
        float s = 0.f;
        #pragma unroll
        for (int r = 0; r < 8; ++r) s += lr[((hq * 8 + r) * 16) + ql];
        li[t] = (hq * 16 + ql < kNQ) ? 1.0f / s : 0.f;
    }
    __syncthreads();

    // ---- final: sum 8 s-group partials, normalize, store ----
    float* ob = out + (size_t)b * OUT_PER_B;
    #pragma unroll
    for (int o = t; o < 2 * 16 * 128; o += THREADS) {
        int hq = o >> 11, ql = (o >> 7) & 15, d = o & 127;
        int q = hq * 16 + ql;
        if (q < kNQ) {
            float s = 0.f;
            #pragma unroll
            for (int r = 0; r < 8; ++r)
                s += red[((hq * 8 + r) * 16 + ql) * 128 + d];
            ob[q * kD + d] = s * li[q];
        }
    }
}

extern "C" void kernel_launch(void* const* d_in, const int* in_sizes, int n_in,
                              void* d_out, int out_size) {
    const float* x    = (const float*)d_in[0];
    const float* qe   = (const float*)d_in[1];
    const int*   ques = (const int*)d_in[2];
    const int*   mask = (const int*)d_in[3];
    float* out = (float*)d_out;

    cudaFuncSetAttribute(AttentionPooling_main,
                         cudaFuncAttributeMaxDynamicSharedMemorySize, SMEM_BYTES);
    AttentionPooling_main<<<kB, THREADS, SMEM_BYTES>>>(x, qe, ques, mask, out);
}